// round 2
// baseline (speedup 1.0000x reference)
#include <cuda_runtime.h>

#define Bv 32
#define Tv 1000
#define DINv 64
#define Hv 1024

#define NBG 4
#define NJG 32
#define BTILE 8
#define JTILE 32
#define NTHREADS 256
#define NWARPS 8
#define KSLICE (Hv / NWARPS)   // 128

#define WS_STRIDE 33
#define HS_STRIDE 10
#define WIS_STRIDE 33

#define GRID (NBG * NJG)       // 128 CTAs, one per SM, all co-resident

__device__ unsigned int g_bar;

struct Smem {
    float  Ws[Hv * WS_STRIDE];          // W slice, [k][jl], pad 33
    float  Wi[DINv * WIS_STRIDE];       // W_in slice, [kk][jl], pad 33
    float  h_s[Hv * HS_STRIDE];         // h(t-1) tile, [k][b], pad 10
    float  x_s[BTILE * DINv];           // x tile for step t
    float2 red[NWARPS][4][JTILE + 1];   // k-split partials
};
// sizeof(Smem) = 195072 bytes (~190.5 KB) < 227 KB limit

__global__ void esn_reset_kernel() { g_bar = 0u; }

__global__ void __launch_bounds__(NTHREADS, 1)
esn_scan_kernel(const float* __restrict__ x, const float* __restrict__ Wiw,
                const float* __restrict__ Wib, const float* __restrict__ W,
                float* __restrict__ out)
{
    extern __shared__ unsigned char smem_raw[];
    Smem& sm = *reinterpret_cast<Smem*>(smem_raw);

    const int tid  = threadIdx.x;
    const int lane = tid & 31;          // jl in epilogue / GEMM
    const int wid  = tid >> 5;          // warp id: k-slice in GEMM, b in epilogue
    const int bg = blockIdx.x & (NBG - 1);
    const int jg = blockIdx.x >> 2;
    const int b0 = bg * BTILE;
    const int j0 = jg * JTILE;

    // ---- One-time: load resident W slice (coalesced reads, conflict-free STS) ----
    for (int idx = tid; idx < JTILE * Hv; idx += NTHREADS) {
        int jl = idx >> 10;
        int k  = idx & (Hv - 1);
        sm.Ws[k * WS_STRIDE + jl] = W[(j0 + jl) * Hv + k];
    }
    for (int idx = tid; idx < JTILE * DINv; idx += NTHREADS) {
        int jl = idx >> 6;
        int kk = idx & (DINv - 1);
        sm.Wi[kk * WIS_STRIDE + jl] = Wiw[(j0 + jl) * DINv + kk];
    }
    const float biasr = Wib[j0 + lane];

    // h-loader thread mapping: 512B fully-coalesced LDG.128, conflict-free STS
    const int hl_b  = tid & 7;
    const int hl_k4 = tid >> 3;         // 0..31

    __syncthreads();

    const float lr  = 0.9f;
    const float olr = 1.0f - lr;

    for (int t = 0; t < Tv; ++t) {
        // ---- Stage x tile for this step (h-independent, before barrier wait) ----
        {
            const float* xp = x + ((b0 + wid) * Tv + t) * DINv;
            sm.x_s[wid * DINv + lane]      = xp[lane];
            sm.x_s[wid * DINv + lane + 32] = xp[lane + 32];
        }
        __syncthreads();

        // ---- Input projection u0 = x@W_in^T + b (overlaps barrier latency) ----
        float u0 = biasr;
        {
            const float* xr  = &sm.x_s[wid * DINv];
            const float* wir = &sm.Wi[lane];
            #pragma unroll
            for (int kk = 0; kk < DINv; ++kk)
                u0 += xr[kk] * wir[kk * WIS_STRIDE];
        }

        float ssum  = 0.0f;
        float hprev = 0.0f;

        if (t > 0) {
            // ---- Device-wide barrier: wait until all CTAs finished step t-1 ----
            if (tid == 0) {
                unsigned tgt = (unsigned)t * GRID;
                unsigned v;
                do {
                    asm volatile("ld.acquire.gpu.global.u32 %0, [%1];"
                                 : "=r"(v) : "l"(&g_bar));
                } while (v < tgt);
            }
            __syncthreads();

            // ---- Load h(t-1)[b0..b0+7][:] from out column t-1 into SMEM [k][b] ----
            {
                const float4* hsrc =
                    (const float4*)(out + ((size_t)(b0 + hl_b) * Tv + (t - 1)) * Hv);
                #pragma unroll
                for (int i = 0; i < 8; ++i) {
                    int k4 = hl_k4 + 32 * i;
                    float4 v = __ldcg(hsrc + k4);
                    int k = k4 << 2;
                    sm.h_s[(k + 0) * HS_STRIDE + hl_b] = v.x;
                    sm.h_s[(k + 1) * HS_STRIDE + hl_b] = v.y;
                    sm.h_s[(k + 2) * HS_STRIDE + hl_b] = v.z;
                    sm.h_s[(k + 3) * HS_STRIDE + hl_b] = v.w;
                }
            }
            __syncthreads();

            // ---- Recurrent GEMM: warp 'wid' handles K-slice, lane = output j ----
            // acc: 4 packed float2 over the 8 batch rows; fma.rn.f32x2 => FFMA2
            unsigned long long a0 = 0ull, a1 = 0ull, a2 = 0ull, a3 = 0ull;
            {
                const float* wsp = &sm.Ws[(wid * KSLICE) * WS_STRIDE + lane];
                const float* hsp = &sm.h_s[(wid * KSLICE) * HS_STRIDE];
                #pragma unroll 8
                for (int k = 0; k < KSLICE; ++k) {
                    float w = wsp[k * WS_STRIDE];
                    unsigned long long w2;
                    asm("mov.b64 %0, {%1, %1};" : "=l"(w2) : "f"(w));
                    const unsigned long long* hp =
                        (const unsigned long long*)(hsp + k * HS_STRIDE);
                    unsigned long long h01 = hp[0];
                    unsigned long long h23 = hp[1];
                    unsigned long long h45 = hp[2];
                    unsigned long long h67 = hp[3];
                    asm("fma.rn.f32x2 %0, %1, %2, %0;" : "+l"(a0) : "l"(w2), "l"(h01));
                    asm("fma.rn.f32x2 %0, %1, %2, %0;" : "+l"(a1) : "l"(w2), "l"(h23));
                    asm("fma.rn.f32x2 %0, %1, %2, %0;" : "+l"(a2) : "l"(w2), "l"(h45));
                    asm("fma.rn.f32x2 %0, %1, %2, %0;" : "+l"(a3) : "l"(w2), "l"(h67));
                }
            }

            // ---- K-split reduction through SMEM ----
            float2 f0, f1, f2, f3;
            asm("mov.b64 {%0, %1}, %2;" : "=f"(f0.x), "=f"(f0.y) : "l"(a0));
            asm("mov.b64 {%0, %1}, %2;" : "=f"(f1.x), "=f"(f1.y) : "l"(a1));
            asm("mov.b64 {%0, %1}, %2;" : "=f"(f2.x), "=f"(f2.y) : "l"(a2));
            asm("mov.b64 {%0, %1}, %2;" : "=f"(f3.x), "=f"(f3.y) : "l"(a3));
            sm.red[wid][0][lane] = f0;
            sm.red[wid][1][lane] = f1;
            sm.red[wid][2][lane] = f2;
            sm.red[wid][3][lane] = f3;
            __syncthreads();

            {
                const int p = wid >> 1;
                const int c = wid & 1;
                #pragma unroll
                for (int w = 0; w < NWARPS; ++w) {
                    float2 v = sm.red[w][p][lane];
                    ssum += c ? v.y : v.x;
                }
            }
            hprev = sm.h_s[(j0 + lane) * HS_STRIDE + wid];
        }

        // ---- Epilogue: thread (b=wid, j=j0+lane) ----
        float u    = u0 + ssum;
        float hnew = olr * hprev + lr * tanhf(u);
        out[((size_t)(b0 + wid) * Tv + t) * Hv + j0 + lane] = hnew;

        // ---- Arrive: make h(t) visible, bump global counter ----
        __threadfence();
        __syncthreads();
        if (tid == 0) atomicAdd(&g_bar, 1u);
    }
}

extern "C" void kernel_launch(void* const* d_in, const int* in_sizes, int n_in,
                              void* d_out, int out_size)
{
    const float* x   = (const float*)d_in[0];  // [32,1000,64]
    const float* Wiw = (const float*)d_in[1];  // [1024,64]
    const float* Wib = (const float*)d_in[2];  // [1024]
    const float* W   = (const float*)d_in[3];  // [1024,1024]
    float* out = (float*)d_out;                // [32,1000,1024]

    const size_t smem = sizeof(Smem);
    cudaFuncSetAttribute(esn_scan_kernel,
                         cudaFuncAttributeMaxDynamicSharedMemorySize, (int)smem);

    esn_reset_kernel<<<1, 1>>>();
    esn_scan_kernel<<<GRID, NTHREADS, smem>>>(x, Wiw, Wib, W, out);
}

// round 3
// speedup vs baseline: 1.0233x; 1.0233x over previous
#include <cuda_runtime.h>

#define Bv 32
#define Tv 1000
#define DINv 64
#define Hv 1024

#define NBG 4
#define NJG 32
#define BTILE 8
#define JTILE 32
#define NTHREADS 256
#define NWARPS 8
#define KSLICE (Hv / NWARPS)   // 128

#define WS_STRIDE 36           // floats per k-row of W tile (32 + 4 pad, keeps LDS.128 16B-aligned)
#define HS_STRIDE 10           // floats per k-row of h tile (8 + 2 pad, conflict-free staging STS)
#define RED_JS 34

#define GRID (NBG * NJG)       // 128 CTAs, one per SM, all co-resident

__device__ unsigned int g_bar;

struct Smem {
    float Ws[Hv * WS_STRIDE];                 // 147456 B : W slice [k][j]
    float h_s[Hv * HS_STRIDE];                // 40960 B  : h(t-1) tile [k][b]
    float red[NWARPS][BTILE][RED_JS];         // 8704 B   : k-split partials [w][b][j]
};
// total = 197120 B < 227 KB

__global__ void esn_reset_kernel() { g_bar = 0u; }

// ---------------------------------------------------------------------------
// Phase 1: u_in[b,t,:] = x[b,t,:] @ W_in^T + b  written into `out`
// grid = (B*T)/16 = 2000 blocks, 256 threads
// ---------------------------------------------------------------------------
__global__ void __launch_bounds__(256)
esn_uin_kernel(const float* __restrict__ x, const float* __restrict__ Wiw,
               const float* __restrict__ Wib, float* __restrict__ out)
{
    __shared__ float2 xs2[DINv * 18];         // [k][r] duplicated pairs (v,v), 16 rows + pad
    __shared__ float  wis[DINv * 130];        // [k][j] transposed Wi chunk, 128 j + pad

    const int tid = threadIdx.x;
    const int R0  = blockIdx.x * 16;          // 16 (b,t) rows per block

    // load x rows, duplicated: xs2[k][r] = (x[R0+r][k], same)
    {
        const int kk = tid & 63, r4 = tid >> 6;
        #pragma unroll
        for (int i = 0; i < 4; ++i) {
            int r = r4 * 4 + i;
            float v = x[(size_t)(R0 + r) * DINv + kk];
            xs2[kk * 18 + r] = make_float2(v, v);
        }
    }

    const int jp = tid & 63;                  // j-pair index: j = 2*jp, 2*jp+1
    const int rq = tid >> 6;                  // row quad: rows rq*4 .. rq*4+3

    const unsigned wis_s = (unsigned)__cvta_generic_to_shared(wis);
    const unsigned xs_s  = (unsigned)__cvta_generic_to_shared(xs2);

    for (int jc = 0; jc < 8; ++jc) {          // 8 chunks of 128 j
        __syncthreads();
        for (int idx = tid; idx < 128 * DINv; idx += 256) {
            int jj = idx >> 6, kk = idx & 63;
            wis[kk * 130 + jj] = Wiw[(jc * 128 + jj) * DINv + kk];
        }
        __syncthreads();

        float2 bias2 = *(const float2*)&Wib[jc * 128 + 2 * jp];
        unsigned long long acc[4], b2;
        asm("mov.b64 %0,{%1,%2};" : "=l"(b2) : "f"(bias2.x), "f"(bias2.y));
        #pragma unroll
        for (int r = 0; r < 4; ++r) acc[r] = b2;

        unsigned wa = wis_s + (2 * jp) * 4;
        unsigned xa = xs_s + (rq * 4) * 8;
        #pragma unroll 8
        for (int k = 0; k < DINv; ++k) {
            unsigned long long w01, x0, x1, x2, x3;
            asm("ld.shared.u64 %0,[%1];" : "=l"(w01) : "r"(wa));
            asm("ld.shared.u64 %0,[%1];" : "=l"(x0) : "r"(xa));
            asm("ld.shared.u64 %0,[%1+8];" : "=l"(x1) : "r"(xa));
            asm("ld.shared.u64 %0,[%1+16];" : "=l"(x2) : "r"(xa));
            asm("ld.shared.u64 %0,[%1+24];" : "=l"(x3) : "r"(xa));
            asm("fma.rn.f32x2 %0,%1,%2,%0;" : "+l"(acc[0]) : "l"(w01), "l"(x0));
            asm("fma.rn.f32x2 %0,%1,%2,%0;" : "+l"(acc[1]) : "l"(w01), "l"(x1));
            asm("fma.rn.f32x2 %0,%1,%2,%0;" : "+l"(acc[2]) : "l"(w01), "l"(x2));
            asm("fma.rn.f32x2 %0,%1,%2,%0;" : "+l"(acc[3]) : "l"(w01), "l"(x3));
            wa += 130 * 4;
            xa += 18 * 8;
        }

        #pragma unroll
        for (int r = 0; r < 4; ++r) {
            float fx, fy;
            asm("mov.b64 {%0,%1},%2;" : "=f"(fx), "=f"(fy) : "l"(acc[r]));
            float2* op = (float2*)&out[(size_t)(R0 + rq * 4 + r) * Hv + jc * 128 + 2 * jp];
            *op = make_float2(fx, fy);
        }
    }
}

// ---------------------------------------------------------------------------
// Phase 2: persistent scan. CTA owns (8 batch) x (32 j) tile; W slice in SMEM.
// ---------------------------------------------------------------------------
__global__ void __launch_bounds__(NTHREADS, 1)
esn_scan_kernel(const float* __restrict__ W, float* __restrict__ out)
{
    extern __shared__ unsigned char smem_raw[];
    Smem& sm = *reinterpret_cast<Smem*>(smem_raw);

    const int tid  = threadIdx.x;
    const int lane = tid & 31;
    const int wid  = tid >> 5;          // k-slice in GEMM; batch row in epilogue
    const int jq   = lane & 7;          // j-quad: j = 4*jq .. 4*jq+3
    const int bg   = lane >> 3;         // b-pair: b = 2*bg, 2*bg+1
    const int bg0  = blockIdx.x & (NBG - 1);
    const int jg   = blockIdx.x >> 2;
    const int b0   = bg0 * BTILE;
    const int j0   = jg * JTILE;

    // one-time W slice load: [k][j], stride 36 (4-way STS conflict, once)
    for (int idx = tid; idx < JTILE * Hv; idx += NTHREADS) {
        int jl = idx >> 10;
        int k  = idx & (Hv - 1);
        sm.Ws[k * WS_STRIDE + jl] = W[(size_t)(j0 + jl) * Hv + k];
    }

    // h staging thread mapping (conflict-free STS @ stride 10, coalesced-ish LDG)
    const int hl_b  = tid & 7;
    const int hl_k4 = tid >> 3;

    const unsigned ws_s  = (unsigned)__cvta_generic_to_shared(sm.Ws)
                           + ((wid * KSLICE) * WS_STRIDE + 4 * jq) * 4;
    const unsigned hs_s  = (unsigned)__cvta_generic_to_shared(sm.h_s)
                           + ((wid * KSLICE) * HS_STRIDE + 2 * bg) * 4;

    __syncthreads();

    const float lr  = 0.9f;
    const float olr = 1.0f - lr;

    for (int t = 0; t < Tv; ++t) {
        // prefetch u_in (h-independent; own tile, no race)
        const float u0 = out[((size_t)(b0 + wid) * Tv + t) * Hv + j0 + lane];

        float ssum  = 0.0f;
        float hprev = 0.0f;

        if (t > 0) {
            // device-wide step barrier
            if (tid == 0) {
                unsigned tgt = (unsigned)t * GRID;
                unsigned v;
                do {
                    asm volatile("ld.acquire.gpu.global.u32 %0, [%1];"
                                 : "=r"(v) : "l"(&g_bar));
                } while (v < tgt);
            }
            __syncthreads();

            // gather h(t-1)[b0..b0+7][:] -> SMEM [k][b]
            {
                const float4* hsrc =
                    (const float4*)(out + ((size_t)(b0 + hl_b) * Tv + (t - 1)) * Hv);
                #pragma unroll
                for (int i = 0; i < 8; ++i) {
                    int k4 = hl_k4 + 32 * i;
                    float4 v = __ldcg(hsrc + k4);
                    int k = k4 << 2;
                    sm.h_s[(k + 0) * HS_STRIDE + hl_b] = v.x;
                    sm.h_s[(k + 1) * HS_STRIDE + hl_b] = v.y;
                    sm.h_s[(k + 2) * HS_STRIDE + hl_b] = v.z;
                    sm.h_s[(k + 3) * HS_STRIDE + hl_b] = v.w;
                }
            }
            __syncthreads();

            // recurrent GEMM: per k = 1 LDS.128(W) + 1 LDS.64(h) + 2 packs + 4 FFMA2
            unsigned long long a0 = 0ull, a1 = 0ull, a2 = 0ull, a3 = 0ull;
            {
                unsigned wa = ws_s, ha = hs_s;
                #pragma unroll 8
                for (int k = 0; k < KSLICE; ++k) {
                    unsigned long long w01, w23, h00, h11;
                    unsigned hlo, hhi;
                    asm("ld.shared.v2.u64 {%0,%1},[%2];"
                        : "=l"(w01), "=l"(w23) : "r"(wa));
                    asm("ld.shared.v2.u32 {%0,%1},[%2];"
                        : "=r"(hlo), "=r"(hhi) : "r"(ha));
                    asm("mov.b64 %0,{%1,%1};" : "=l"(h00) : "r"(hlo));
                    asm("mov.b64 %0,{%1,%1};" : "=l"(h11) : "r"(hhi));
                    asm("fma.rn.f32x2 %0,%1,%2,%0;" : "+l"(a0) : "l"(w01), "l"(h00));
                    asm("fma.rn.f32x2 %0,%1,%2,%0;" : "+l"(a1) : "l"(w23), "l"(h00));
                    asm("fma.rn.f32x2 %0,%1,%2,%0;" : "+l"(a2) : "l"(w01), "l"(h11));
                    asm("fma.rn.f32x2 %0,%1,%2,%0;" : "+l"(a3) : "l"(w23), "l"(h11));
                    wa += WS_STRIDE * 4;
                    ha += HS_STRIDE * 4;
                }
            }

            // k-split partials -> SMEM  red[w][b][j] (float2 over j)
            {
                float f0x, f0y, f1x, f1y, f2x, f2y, f3x, f3y;
                asm("mov.b64 {%0,%1},%2;" : "=f"(f0x), "=f"(f0y) : "l"(a0));
                asm("mov.b64 {%0,%1},%2;" : "=f"(f1x), "=f"(f1y) : "l"(a1));
                asm("mov.b64 {%0,%1},%2;" : "=f"(f2x), "=f"(f2y) : "l"(a2));
                asm("mov.b64 {%0,%1},%2;" : "=f"(f3x), "=f"(f3y) : "l"(a3));
                float* rp0 = &sm.red[wid][2 * bg][4 * jq];
                float* rp1 = &sm.red[wid][2 * bg + 1][4 * jq];
                *(float2*)(rp0)     = make_float2(f0x, f0y);
                *(float2*)(rp0 + 2) = make_float2(f1x, f1y);
                *(float2*)(rp1)     = make_float2(f2x, f2y);
                *(float2*)(rp1 + 2) = make_float2(f3x, f3y);
            }
            __syncthreads();

            // reduce 8 k-slices for output (b=wid, j=lane)
            #pragma unroll
            for (int w = 0; w < NWARPS; ++w)
                ssum += sm.red[w][wid][lane];

            hprev = sm.h_s[(j0 + lane) * HS_STRIDE + wid];
        }

        // epilogue: h_new = 0.1*h + 0.9*tanh(u_in + h@W^T)
        float u    = u0 + ssum;
        float hnew = olr * hprev + lr * tanhf(u);
        out[((size_t)(b0 + wid) * Tv + t) * Hv + j0 + lane] = hnew;

        __threadfence();
        __syncthreads();
        if (tid == 0) atomicAdd(&g_bar, 1u);
    }
}

extern "C" void kernel_launch(void* const* d_in, const int* in_sizes, int n_in,
                              void* d_out, int out_size)
{
    const float* x   = (const float*)d_in[0];  // [32,1000,64]
    const float* Wiw = (const float*)d_in[1];  // [1024,64]
    const float* Wib = (const float*)d_in[2];  // [1024]
    const float* W   = (const float*)d_in[3];  // [1024,1024]
    float* out = (float*)d_out;                // [32,1000,1024]

    const size_t smem = sizeof(Smem);
    cudaFuncSetAttribute(esn_scan_kernel,
                         cudaFuncAttributeMaxDynamicSharedMemorySize, (int)smem);

    esn_reset_kernel<<<1, 1>>>();
    esn_uin_kernel<<<(Bv * Tv) / 16, 256>>>(x, Wiw, Wib, out);
    esn_scan_kernel<<<GRID, NTHREADS, smem>>>(W, out);
}